// round 3
// baseline (speedup 1.0000x reference)
#include <cuda_runtime.h>
#include <cuda_bf16.h>
#include <cstdint>

// ============================================================
// Problem dims
// ============================================================
#define VOCAB   32000
#define HID     256
#define BATCH   16
#define TLEN    256
#define NROWS   (BATCH * TLEN)     // 4096
#define VS      8                  // vocab splits
#define VSPLIT  (VOCAB / VS)       // 4000
#define CHUNK   80                 // vocab rows per pipeline chunk
#define NCHUNK  (VSPLIT / CHUNK)   // 50
#define GM      256                // A rows per CTA (one batch element)

// ============================================================
// Device scratch (static — no runtime allocation)
// ============================================================
__device__ __nv_bfloat16 g_Wfc_bf16[(size_t)VOCAB * HID];   // 16.4 MB
__device__ __nv_bfloat16 g_hs[(size_t)NROWS * HID];         // 2 MB
__device__ float g_partials[VS * NROWS];
__device__ float g_tlogit[NROWS];

// ============================================================
// PTX helpers (target-neutral: sm_80+ instructions only)
// ============================================================
__device__ __forceinline__ uint32_t smem_to_u32(const void* p) {
    uint32_t a;
    asm("{ .reg .u64 t; cvta.to.shared.u64 t, %1; cvt.u32.u64 %0, t; }" : "=r"(a) : "l"(p));
    return a;
}

__device__ __forceinline__ void cp16(uint32_t smem_dst, const void* gsrc) {
    asm volatile("cp.async.cg.shared.global [%0], [%1], 16;"
                 :: "r"(smem_dst), "l"(gsrc) : "memory");
}
__device__ __forceinline__ void cp_commit() {
    asm volatile("cp.async.commit_group;" ::: "memory");
}
template <int N>
__device__ __forceinline__ void cp_wait() {
    asm volatile("cp.async.wait_group %0;" :: "n"(N) : "memory");
}

__device__ __forceinline__ void ldsm4(uint32_t* r, uint32_t addr) {
    asm volatile("ldmatrix.sync.aligned.m8n8.x4.shared.b16 {%0,%1,%2,%3}, [%4];"
                 : "=r"(r[0]), "=r"(r[1]), "=r"(r[2]), "=r"(r[3]) : "r"(addr));
}

__device__ __forceinline__ void mma16816(float* c, const uint32_t* a, uint32_t b0, uint32_t b1) {
    asm volatile(
        "mma.sync.aligned.m16n8k16.row.col.f32.bf16.bf16.f32 "
        "{%0,%1,%2,%3}, {%4,%5,%6,%7}, {%8,%9}, {%0,%1,%2,%3};"
        : "+f"(c[0]), "+f"(c[1]), "+f"(c[2]), "+f"(c[3])
        : "r"(a[0]), "r"(a[1]), "r"(a[2]), "r"(a[3]), "r"(b0), "r"(b1));
}

// ============================================================
// Kernel 1: Wfc fp32 -> bf16
// ============================================================
__global__ void __launch_bounds__(256) convert_wfc_kernel(const float* __restrict__ Wfc) {
    int idx = blockIdx.x * blockDim.x + threadIdx.x;   // over 2,048,000 float4s
    const float4* src = (const float4*)Wfc;
    float4 v = src[idx];
    __nv_bfloat162* dst = (__nv_bfloat162*)g_Wfc_bf16;
    dst[2 * idx + 0] = __floats2bfloat162_rn(v.x, v.y);
    dst[2 * idx + 1] = __floats2bfloat162_rn(v.z, v.w);
}

// ============================================================
// Kernel 2: RNN scan (one CTA per batch element, fp32)
//   h_new[i] = tanh(Wih[tok][i] + bih[i] + bhh[i] + sum_j Whh[i][j] h[j])
// Whh row i: j in [0,128) in registers, j in [128,256) in SMEM (stride 129,
// conflict-free).
// ============================================================
#define RNN_WS 129
#define RNN_SMEM ((256 * RNN_WS + 256 + 256) * 4)

__global__ void __launch_bounds__(256, 1)
rnn_kernel(const int* __restrict__ inputs, const float* __restrict__ Wih,
           const float* __restrict__ bih, const float* __restrict__ Whh,
           const float* __restrict__ bhh)
{
    extern __shared__ float sm[];
    float* wsm  = sm;                       // 256*129
    float* h_sh = sm + 256 * RNN_WS;        // 256
    int*   toks = (int*)(h_sh + 256);       // 256

    const int b = blockIdx.x;
    const int i = threadIdx.x;

    toks[i] = inputs[b * TLEN + i];

    // SMEM half of Whh: columns [128,256)
    for (int idx = i; idx < 256 * 128; idx += 256) {
        int row = idx >> 7, jj = idx & 127;
        wsm[row * RNN_WS + jj] = Whh[row * 256 + 128 + jj];
    }
    // Register half: columns [0,128)
    float w[128];
    {
        const float4* wr = (const float4*)(Whh + (size_t)i * 256);
#pragma unroll
        for (int k = 0; k < 32; k++) {
            float4 v = wr[k];
            w[4 * k] = v.x; w[4 * k + 1] = v.y; w[4 * k + 2] = v.z; w[4 * k + 3] = v.w;
        }
    }
    const float bsum = bih[i] + bhh[i];
    h_sh[i] = 0.f;
    __syncthreads();

    const float* wrow_s = wsm + i * RNN_WS;

    for (int t = 0; t < TLEN; t++) {
        int tok = toks[t];
        float x = __ldg(Wih + (size_t)tok * 256 + i);

        float a0 = 0.f, a1 = 0.f, a2 = 0.f, a3 = 0.f;
#pragma unroll
        for (int k = 0; k < 128; k += 8) {
            float4 h0 = *(const float4*)(h_sh + k);
            float4 h1 = *(const float4*)(h_sh + k + 4);
            a0 += w[k]     * h0.x + w[k + 1] * h0.y;
            a1 += w[k + 2] * h0.z + w[k + 3] * h0.w;
            a2 += w[k + 4] * h1.x + w[k + 5] * h1.y;
            a3 += w[k + 6] * h1.z + w[k + 7] * h1.w;
        }
#pragma unroll
        for (int k = 0; k < 128; k += 8) {
            float4 h0 = *(const float4*)(h_sh + 128 + k);
            float4 h1 = *(const float4*)(h_sh + 128 + k + 4);
            a0 += wrow_s[k]     * h0.x + wrow_s[k + 1] * h0.y;
            a1 += wrow_s[k + 2] * h0.z + wrow_s[k + 3] * h0.w;
            a2 += wrow_s[k + 4] * h1.x + wrow_s[k + 5] * h1.y;
            a3 += wrow_s[k + 6] * h1.z + wrow_s[k + 7] * h1.w;
        }
        __syncthreads();   // all reads of h_sh done

        float h = tanhf(x + bsum + ((a0 + a1) + (a2 + a3)));
        h_sh[i] = h;
        g_hs[((size_t)b * TLEN + t) * 256 + i] = __float2bfloat16(h);
        __syncthreads();   // h_sh visible for next step
    }
}

// ============================================================
// Kernel 3: FC GEMM (mma.sync bf16) fused with log-sum-exp partials.
// Grid: (16 row-tiles) x (8 vocab splits) = 128 CTAs, 256 threads (8 warps).
// CTA keeps its A tile (256 rows x 256 K, bf16, 528B stride) in SMEM; streams
// its 4000-vocab split in 50 chunks of 80 rows, cp.async double buffered.
// Each warp owns 32 rows (2 m16 tiles); per chunk: 10 n8-tiles, K=256 as
// 16 k16 steps. Epilogue: logit = acc + bfc; running sum += expf(logit);
// capture target logit. Per-(rowtile,vsplit) partials -> g_partials.
//
// SMEM layout (bytes):
//   A   : [0, 135168)             256 rows x 528
//   B0  : [135168, 177408)        80 rows x 528
//   B1  : [177408, 219648)
//   bfc0: [219648, 219968)        80 f32
//   bfc1: [219968, 220288)
// ============================================================
#define AST 528
#define BST 528
#define SM_A  0
#define SM_B0 135168
#define SM_B1 177408
#define SM_F0 219648
#define SM_F1 219968
#define SM_TOT 220288

__global__ void __launch_bounds__(256, 1)
gemm_lse_kernel(const int* __restrict__ targets, const float* __restrict__ bfc)
{
    extern __shared__ char smc[];
    const uint32_t smb = smem_to_u32(smc);
    const int tid = threadIdx.x;
    const int w = tid >> 5;
    const int lid = tid & 31;
    const int rt = blockIdx.x;      // row tile (batch element)
    const int vs = blockIdx.y;      // vocab split
    const int v0 = vs * VSPLIT;

    // ---- chunk loader (B rows + bfc) via cp.async ----
    auto load_chunk = [&](int c, int buf) {
        const char* src = (const char*)(g_Wfc_bf16 + (size_t)(v0 + c * CHUNK) * HID);
        uint32_t dstB = smb + (buf ? SM_B1 : SM_B0);
#pragma unroll
        for (int it = 0; it < 10; it++) {
            int i = it * 256 + tid;               // 2560 x 16B
            int row = i >> 5, cc = i & 31;
            cp16(dstB + row * BST + cc * 16, src + row * 512 + cc * 16);
        }
        if (tid < 20)
            cp16(smb + (buf ? SM_F1 : SM_F0) + tid * 16,
                 (const char*)(bfc + v0 + c * CHUNK) + tid * 16);
    };

    load_chunk(0, 0); cp_commit();

    // ---- A tile: g_hs rows [rt*256, rt*256+256) -> SMEM (stride 528) ----
    {
        const uint4* asrc = (const uint4*)(g_hs + (size_t)rt * GM * HID);
#pragma unroll
        for (int it = 0; it < 32; it++) {
            int i = it * 256 + tid;               // 8192 x 16B
            int row = i >> 5, cc = i & 31;
            *(uint4*)(smc + SM_A + row * AST + cc * 16) = asrc[i];
        }
    }

    load_chunk(1, 1); cp_commit();

    // ---- per-thread row-slot state ----
    // slot s: row = rt*256 + w*32 + (s>>1)*16 + (s&1)*8 + lid/4
    const int rbase = rt * GM + w * 32;
    int tg[4]; float tl[4] = {0.f, 0.f, 0.f, 0.f}; float sums[4] = {0.f, 0.f, 0.f, 0.f};
#pragma unroll
    for (int s = 0; s < 4; s++)
        tg[s] = targets[rbase + (s >> 1) * 16 + (s & 1) * 8 + (lid >> 2)];

    __syncthreads();   // A tile visible to all warps

    // ldmatrix A base: lanes 0-15 -> rows 0-15 col 0; 16-31 -> rows 0-15 col +16B
    const uint32_t aaddr = smb + SM_A + (w * 32 + (lid & 15)) * AST + (lid >> 4) * 16;
    // ldmatrix B base (x4 = 2 n-tiles): n_local = (lid>>4)*8 + (lid&7), k half = (lid>>3)&1
    const uint32_t boff = (((lid >> 4) << 3) + (lid & 7)) * BST + ((lid >> 3) & 1) * 16;

    for (int c = 0; c < NCHUNK; c++) {
        const int buf = c & 1;
        cp_wait<1>();        // chunk c resident
        __syncthreads();

        float acc[2][10][4];
#pragma unroll
        for (int mt = 0; mt < 2; mt++)
#pragma unroll
            for (int nt = 0; nt < 10; nt++)
#pragma unroll
                for (int q = 0; q < 4; q++) acc[mt][nt][q] = 0.f;

        const uint32_t bbase = smb + (buf ? SM_B1 : SM_B0) + boff;

#pragma unroll
        for (int ks = 0; ks < 16; ks++) {
            uint32_t a0[4], a1[4];
            ldsm4(a0, aaddr + ks * 32);
            ldsm4(a1, aaddr + 16 * AST + ks * 32);
            uint32_t b[5][4];
#pragma unroll
            for (int p = 0; p < 5; p++)
                ldsm4(b[p], bbase + p * 16 * BST + ks * 32);
#pragma unroll
            for (int nt = 0; nt < 10; nt++) {
                uint32_t b0 = b[nt >> 1][(nt & 1) * 2];
                uint32_t b1 = b[nt >> 1][(nt & 1) * 2 + 1];
                mma16816(acc[0][nt], a0, b0, b1);
                mma16816(acc[1][nt], a1, b0, b1);
            }
        }

        // ---- epilogue: add bfc, exp-accumulate, capture target logit ----
        const float* fb = (const float*)(smc + (buf ? SM_F1 : SM_F0));
        const int vbase = v0 + c * CHUNK + 2 * (lid & 3);
#pragma unroll
        for (int nt = 0; nt < 10; nt++) {
            float2 f2 = *(const float2*)(fb + nt * 8 + 2 * (lid & 3));
            const int v = vbase + nt * 8;
#pragma unroll
            for (int mt = 0; mt < 2; mt++) {
                float l0 = acc[mt][nt][0] + f2.x;
                float l1 = acc[mt][nt][1] + f2.y;
                float l2 = acc[mt][nt][2] + f2.x;
                float l3 = acc[mt][nt][3] + f2.y;
                sums[mt * 2 + 0] += __expf(l0) + __expf(l1);
                sums[mt * 2 + 1] += __expf(l2) + __expf(l3);
                if (v     == tg[mt * 2])     tl[mt * 2]     = l0;
                if (v + 1 == tg[mt * 2])     tl[mt * 2]     = l1;
                if (v     == tg[mt * 2 + 1]) tl[mt * 2 + 1] = l2;
                if (v + 1 == tg[mt * 2 + 1]) tl[mt * 2 + 1] = l3;
            }
        }

        __syncthreads();   // all reads of buf done before it is refilled
        if (c + 2 < NCHUNK) { load_chunk(c + 2, buf); cp_commit(); }
    }

    // ---- reduce across the 4 lanes of each quad, store partials ----
#pragma unroll
    for (int s = 0; s < 4; s++) {
        float v = sums[s];
        v += __shfl_xor_sync(0xFFFFFFFFu, v, 1);
        v += __shfl_xor_sync(0xFFFFFFFFu, v, 2);
        float t = tl[s];
        t += __shfl_xor_sync(0xFFFFFFFFu, t, 1);
        t += __shfl_xor_sync(0xFFFFFFFFu, t, 2);
        if ((lid & 3) == 0) {
            int r = rbase + (s >> 1) * 16 + (s & 1) * 8 + (lid >> 2);
            g_partials[vs * NROWS + r] = v;
            if ((unsigned)(tg[s] - v0) < (unsigned)VSPLIT) g_tlogit[r] = t;
        }
    }
}

// ============================================================
// Kernel 4: finalize — loss = mean_r [ log(sum_vs partial[vs][r]) - tlogit[r] ]
// Deterministic fixed-order reduction.
// ============================================================
__global__ void __launch_bounds__(1024, 1) finalize_kernel(float* __restrict__ out)
{
    __shared__ float red[1024];
    const int tid = threadIdx.x;
    float local = 0.f;
#pragma unroll
    for (int rr = 0; rr < 4; rr++) {
        int r = rr * 1024 + tid;
        float se = 0.f;
#pragma unroll
        for (int s = 0; s < VS; s++)
            se += g_partials[s * NROWS + r];
        local += logf(se) - g_tlogit[r];
    }
    red[tid] = local;
    __syncthreads();
    for (int o = 512; o > 0; o >>= 1) {
        if (tid < o) red[tid] += red[tid + o];
        __syncthreads();
    }
    if (tid == 0) out[0] = red[0] * (1.0f / NROWS);
}

// ============================================================
// Launch
// ============================================================
extern "C" void kernel_launch(void* const* d_in, const int* in_sizes, int n_in,
                              void* d_out, int out_size)
{
    const int*   inputs  = (const int*)d_in[0];
    const int*   targets = (const int*)d_in[1];
    const float* Wih     = (const float*)d_in[2];
    const float* bih     = (const float*)d_in[3];
    const float* Whh     = (const float*)d_in[4];
    const float* bhh     = (const float*)d_in[5];
    const float* Wfc     = (const float*)d_in[6];
    const float* bfc     = (const float*)d_in[7];

    cudaFuncSetAttribute(rnn_kernel, cudaFuncAttributeMaxDynamicSharedMemorySize, RNN_SMEM);
    cudaFuncSetAttribute(gemm_lse_kernel, cudaFuncAttributeMaxDynamicSharedMemorySize, SM_TOT);

    convert_wfc_kernel<<<(VOCAB * HID / 4) / 256, 256>>>(Wfc);
    rnn_kernel<<<BATCH, 256, RNN_SMEM>>>(inputs, Wih, bih, Whh, bhh);
    dim3 g(BATCH, VS);
    gemm_lse_kernel<<<g, 256, SM_TOT>>>(targets, bfc);
    finalize_kernel<<<1, 1024>>>((float*)d_out);
}

// round 7
// speedup vs baseline: 1.1125x; 1.1125x over previous
#include <cuda_runtime.h>
#include <cuda_bf16.h>
#include <cstdint>

// ============================================================
// Problem dims
// ============================================================
#define VOCAB   32000
#define HID     256
#define BATCH   16
#define TLEN    256
#define NROWS   (BATCH * TLEN)     // 4096
#define NVS     16                 // vocab splits
#define VSPLIT  (VOCAB / NVS)      // 2000
#define CHUNK   80                 // vocab rows per pipeline chunk
#define NCHUNK  (VSPLIT / CHUNK)   // 25
#define NTILES  32                 // row tiles of 128
#define NTASKS  (NTILES * NVS)     // 512
#define NWORKER 128
#define GRID    (16 + NWORKER)     // 144 CTAs, single wave

// ============================================================
// Device scratch (static — no runtime allocation)
// ============================================================
__device__ __nv_bfloat16 g_Wfc_bf16[(size_t)VOCAB * HID];   // 16.4 MB
__device__ __nv_bfloat16 g_hs[(size_t)NROWS * HID];         // 2 MB
__device__ float g_partials[NVS * NROWS];
__device__ float g_tlogit[NROWS];
__device__ int   g_tile_ready[NTILES];
__device__ int   g_ticket;

// ============================================================
// PTX helpers (target-neutral: sm_80+ instructions only)
// ============================================================
__device__ __forceinline__ uint32_t smem_to_u32(const void* p) {
    uint32_t a;
    asm("{ .reg .u64 t; cvta.to.shared.u64 t, %1; cvt.u32.u64 %0, t; }" : "=r"(a) : "l"(p));
    return a;
}

__device__ __forceinline__ void cp16(uint32_t smem_dst, const void* gsrc) {
    asm volatile("cp.async.cg.shared.global [%0], [%1], 16;"
                 :: "r"(smem_dst), "l"(gsrc) : "memory");
}
__device__ __forceinline__ void cp_commit() {
    asm volatile("cp.async.commit_group;" ::: "memory");
}
template <int N>
__device__ __forceinline__ void cp_wait() {
    asm volatile("cp.async.wait_group %0;" :: "n"(N) : "memory");
}

__device__ __forceinline__ void ldsm4(uint32_t* r, uint32_t addr) {
    asm volatile("ldmatrix.sync.aligned.m8n8.x4.shared.b16 {%0,%1,%2,%3}, [%4];"
                 : "=r"(r[0]), "=r"(r[1]), "=r"(r[2]), "=r"(r[3]) : "r"(addr));
}

__device__ __forceinline__ void mma16816(float* c, const uint32_t* a, uint32_t b0, uint32_t b1) {
    asm volatile(
        "mma.sync.aligned.m16n8k16.row.col.f32.bf16.bf16.f32 "
        "{%0,%1,%2,%3}, {%4,%5,%6,%7}, {%8,%9}, {%0,%1,%2,%3};"
        : "+f"(c[0]), "+f"(c[1]), "+f"(c[2]), "+f"(c[3])
        : "r"(a[0]), "r"(a[1]), "r"(a[2]), "r"(a[3]), "r"(b0), "r"(b1));
}

// ============================================================
// Kernel 1: Wfc fp32 -> bf16, plus per-replay reset of flags/ticket
// ============================================================
__global__ void __launch_bounds__(256) convert_wfc_kernel(const float* __restrict__ Wfc) {
    if (blockIdx.x == 0) {
        if (threadIdx.x < NTILES) g_tile_ready[threadIdx.x] = 0;
        if (threadIdx.x == NTILES) g_ticket = 0;
    }
    int idx = blockIdx.x * blockDim.x + threadIdx.x;   // over 2,048,000 float4s
    const float4* src = (const float4*)Wfc;
    float4 v = src[idx];
    __nv_bfloat162* dst = (__nv_bfloat162*)g_Wfc_bf16;
    dst[2 * idx + 0] = __floats2bfloat162_rn(v.x, v.y);
    dst[2 * idx + 1] = __floats2bfloat162_rn(v.z, v.w);
}

// ============================================================
// Fused kernel SMEM layout (worker role), bytes:
//   A   : [0, 67584)         128 rows x 528
//   B0  : [67584, 109824)    80 rows x 528
//   B1  : [109824, 152064)
//   bfc0: [152064, 152384)   80 f32
//   bfc1: [152384, 152704)
//   task: [152704, 152708)
// RNN role reuses the same allocation: Whh-half 132096 + h ping-pong 2048
// + toks 1024 = 135168 bytes.
// ============================================================
#define AST   528
#define BST   528
#define SM_A    0
#define SM_B0   67584
#define SM_B1   109824
#define SM_F0   152064
#define SM_F1   152384
#define SM_TASK 152704
#define SM_TOT  152768

#define RNN_WS 129

// ---------------- RNN role ----------------
__device__ __forceinline__ void rnn_role(
    char* smc, const int* __restrict__ inputs, const float* __restrict__ Wih,
    const float* __restrict__ bih, const float* __restrict__ Whh,
    const float* __restrict__ bhh)
{
    float* sm   = (float*)smc;
    float* wsm  = sm;                       // 256*129
    float* hbuf = sm + 256 * RNN_WS;        // 2 x 256 (ping-pong)
    int*   toks = (int*)(hbuf + 512);       // 256

    const int b = blockIdx.x;
    const int i = threadIdx.x;

    toks[i] = inputs[b * TLEN + i];

    // SMEM half of Whh: columns [128,256), stride 129 (conflict-free)
    for (int idx = i; idx < 256 * 128; idx += 256) {
        int row = idx >> 7, jj = idx & 127;
        wsm[row * RNN_WS + jj] = Whh[row * 256 + 128 + jj];
    }
    // Register half: columns [0,128)
    float w[128];
    {
        const float4* wr = (const float4*)(Whh + (size_t)i * 256);
#pragma unroll
        for (int k = 0; k < 32; k++) {
            float4 v = wr[k];
            w[4 * k] = v.x; w[4 * k + 1] = v.y; w[4 * k + 2] = v.z; w[4 * k + 3] = v.w;
        }
    }
    const float bsum = bih[i] + bhh[i];
    hbuf[i] = 0.f; hbuf[256 + i] = 0.f;
    __syncthreads();

    const float* wrow_s = wsm + i * RNN_WS;
    int cur = 0;

    for (int t = 0; t < TLEN; t++) {
        const float* h_sh = hbuf + cur * 256;
        int tok = toks[t];
        float x = __ldg(Wih + (size_t)tok * 256 + i);

        float a0 = 0.f, a1 = 0.f, a2 = 0.f, a3 = 0.f;
#pragma unroll
        for (int k = 0; k < 128; k += 8) {
            float4 h0 = *(const float4*)(h_sh + k);
            float4 h1 = *(const float4*)(h_sh + k + 4);
            a0 += w[k]     * h0.x + w[k + 1] * h0.y;
            a1 += w[k + 2] * h0.z + w[k + 3] * h0.w;
            a2 += w[k + 4] * h1.x + w[k + 5] * h1.y;
            a3 += w[k + 6] * h1.z + w[k + 7] * h1.w;
        }
#pragma unroll
        for (int k = 0; k < 128; k += 8) {
            float4 h0 = *(const float4*)(h_sh + 128 + k);
            float4 h1 = *(const float4*)(h_sh + 128 + k + 4);
            a0 += wrow_s[k]     * h0.x + wrow_s[k + 1] * h0.y;
            a1 += wrow_s[k + 2] * h0.z + wrow_s[k + 3] * h0.w;
            a2 += wrow_s[k + 4] * h1.x + wrow_s[k + 5] * h1.y;
            a3 += wrow_s[k + 6] * h1.z + wrow_s[k + 7] * h1.w;
        }

        float h = tanhf(x + bsum + ((a0 + a1) + (a2 + a3)));
        hbuf[(cur ^ 1) * 256 + i] = h;                            // write next buffer
        g_hs[((size_t)b * TLEN + t) * 256 + i] = __float2bfloat16(h);

        if (t == 127 || t == 255) __threadfence();                // publish hs stores
        __syncthreads();                                          // single bar per step
        if (i == 0 && (t == 127 || t == 255))
            atomicExch(&g_tile_ready[(t == 127) ? b : 16 + b], 1);
        cur ^= 1;
    }
}

// ---------------- GEMM worker role ----------------
__device__ __forceinline__ void load_chunk(char* smc, uint32_t smb, int tid,
                                           int v0, int c, int buf,
                                           const float* __restrict__ bfc)
{
    const char* src = (const char*)(g_Wfc_bf16 + (size_t)(v0 + c * CHUNK) * HID);
    uint32_t dstB = smb + (buf ? SM_B1 : SM_B0);
#pragma unroll
    for (int it = 0; it < 10; it++) {
        int i = it * 256 + tid;               // 2560 x 16B
        int row = i >> 5, cc = i & 31;
        cp16(dstB + row * BST + cc * 16, src + row * 512 + cc * 16);
    }
    if (tid < 20)
        cp16(smb + (buf ? SM_F1 : SM_F0) + tid * 16,
             (const char*)(bfc + v0 + c * CHUNK) + tid * 16);
}

__device__ __forceinline__ void worker_role(
    char* smc, const int* __restrict__ targets, const float* __restrict__ bfc)
{
    const uint32_t smb = smem_to_u32(smc);
    const int tid = threadIdx.x;
    const int w = tid >> 5;
    const int lid = tid & 31;
    int* s_task = (int*)(smc + SM_TASK);

    // ldmatrix A base: warp owns 16 rows (one m-tile)
    const uint32_t aaddr = smb + SM_A + (w * 16 + (lid & 15)) * AST + (lid >> 4) * 16;
    // ldmatrix B base (x4 = 2 n-tiles)
    const uint32_t boff = (((lid >> 4) << 3) + (lid & 7)) * BST + ((lid >> 3) & 1) * 16;

    for (;;) {
        if (tid == 0) *s_task = atomicAdd(&g_ticket, 1);
        __syncthreads();
        const int task = *s_task;
        if (task >= NTASKS) break;

        const int i_tile = task >> 4;               // 0..31, first halves first
        const int vs = task & 15;
        const int base = (i_tile < 16) ? i_tile * 256 : (i_tile - 16) * 256 + 128;
        const int v0 = vs * VSPLIT;

        // prefetch B chunks 0,1 while waiting for the tile
        load_chunk(smc, smb, tid, v0, 0, 0, bfc); cp_commit();
        load_chunk(smc, smb, tid, v0, 1, 1, bfc); cp_commit();

        if (tid == 0)
            while (atomicAdd(&g_tile_ready[i_tile], 0) == 0) __nanosleep(512);
        __syncthreads();
        __threadfence();   // acquire: hs stores visible before we read them

        // A tile: 128 rows x 256 K bf16 -> SMEM stride 528
        {
            const uint4* asrc = (const uint4*)(g_hs + (size_t)base * HID);
#pragma unroll
            for (int it = 0; it < 16; it++) {
                int i = it * 256 + tid;               // 4096 x 16B
                int row = i >> 5, cc = i & 31;
                *(uint4*)(smc + SM_A + row * AST + cc * 16) = asrc[i];
            }
        }

        const int rbase = base + w * 16;
        int tg[2]; float tl[2] = {0.f, 0.f}; float sums[2] = {0.f, 0.f};
        tg[0] = targets[rbase + (lid >> 2)];
        tg[1] = targets[rbase + 8 + (lid >> 2)];

        __syncthreads();   // A tile visible

        for (int c = 0; c < NCHUNK; c++) {
            const int buf = c & 1;
            cp_wait<1>();        // one group committed per iter -> chunk c resident
            __syncthreads();

            float acc[10][4];
#pragma unroll
            for (int nt = 0; nt < 10; nt++)
#pragma unroll
                for (int q = 0; q < 4; q++) acc[nt][q] = 0.f;

            const uint32_t bbase = smb + (buf ? SM_B1 : SM_B0) + boff;

#pragma unroll
            for (int ks = 0; ks < 16; ks++) {
                uint32_t a0[4];
                ldsm4(a0, aaddr + ks * 32);
                uint32_t bfr[5][4];
#pragma unroll
                for (int p = 0; p < 5; p++)
                    ldsm4(bfr[p], bbase + p * 16 * BST + ks * 32);
#pragma unroll
                for (int nt = 0; nt < 10; nt++)
                    mma16816(acc[nt], a0, bfr[nt >> 1][(nt & 1) * 2], bfr[nt >> 1][(nt & 1) * 2 + 1]);
            }

            // epilogue: add bfc, exp-accumulate, capture target logit
            const float* fb = (const float*)(smc + (buf ? SM_F1 : SM_F0));
            const int vbase = v0 + c * CHUNK + 2 * (lid & 3);
#pragma unroll
            for (int nt = 0; nt < 10; nt++) {
                float2 f2 = *(const float2*)(fb + nt * 8 + 2 * (lid & 3));
                const int v = vbase + nt * 8;
                float l0 = acc[nt][0] + f2.x;
                float l1 = acc[nt][1] + f2.y;
                float l2 = acc[nt][2] + f2.x;
                float l3 = acc[nt][3] + f2.y;
                sums[0] += __expf(l0) + __expf(l1);
                sums[1] += __expf(l2) + __expf(l3);
                if (v     == tg[0]) tl[0] = l0;
                if (v + 1 == tg[0]) tl[0] = l1;
                if (v     == tg[1]) tl[1] = l2;
                if (v + 1 == tg[1]) tl[1] = l3;
            }

            __syncthreads();   // buf reads done before refill
            if (c + 2 < NCHUNK) load_chunk(smc, smb, tid, v0, c + 2, buf, bfc);
            cp_commit();       // unconditional: keeps wait_group accounting exact
        }

        // reduce across quad lanes, store per-task partials
#pragma unroll
        for (int s = 0; s < 2; s++) {
            float v = sums[s];
            v += __shfl_xor_sync(0xFFFFFFFFu, v, 1);
            v += __shfl_xor_sync(0xFFFFFFFFu, v, 2);
            float t = tl[s];
            t += __shfl_xor_sync(0xFFFFFFFFu, t, 1);
            t += __shfl_xor_sync(0xFFFFFFFFu, t, 2);
            if ((lid & 3) == 0) {
                int r = rbase + s * 8 + (lid >> 2);
                g_partials[vs * NROWS + r] = v;
                if ((unsigned)(tg[s] - v0) < (unsigned)VSPLIT) g_tlogit[r] = t;
            }
        }
        __syncthreads();   // partial writes / A reuse ordering before next task
    }
}

// ---------------- fused kernel ----------------
__global__ void __launch_bounds__(256, 1)
fused_kernel(const int* __restrict__ inputs, const int* __restrict__ targets,
             const float* __restrict__ Wih, const float* __restrict__ bih,
             const float* __restrict__ Whh, const float* __restrict__ bhh,
             const float* __restrict__ bfc)
{
    extern __shared__ char smc[];
    if (blockIdx.x < 16)
        rnn_role(smc, inputs, Wih, bih, Whh, bhh);
    else
        worker_role(smc, targets, bfc);
}

// ============================================================
// Finalize: loss = mean_r [ log(sum_vs partial[vs][r]) - tlogit[r] ]
// ============================================================
__global__ void __launch_bounds__(1024, 1) finalize_kernel(float* __restrict__ out)
{
    __shared__ float red[1024];
    const int tid = threadIdx.x;
    float local = 0.f;
#pragma unroll
    for (int rr = 0; rr < 4; rr++) {
        int r = rr * 1024 + tid;
        float se = 0.f;
#pragma unroll
        for (int s = 0; s < NVS; s++)
            se += g_partials[s * NROWS + r];
        local += logf(se) - g_tlogit[r];
    }
    red[tid] = local;
    __syncthreads();
    for (int o = 512; o > 0; o >>= 1) {
        if (tid < o) red[tid] += red[tid + o];
        __syncthreads();
    }
    if (tid == 0) out[0] = red[0] * (1.0f / NROWS);
}

// ============================================================
// Launch
// ============================================================
extern "C" void kernel_launch(void* const* d_in, const int* in_sizes, int n_in,
                              void* d_out, int out_size)
{
    const int*   inputs  = (const int*)d_in[0];
    const int*   targets = (const int*)d_in[1];
    const float* Wih     = (const float*)d_in[2];
    const float* bih     = (const float*)d_in[3];
    const float* Whh     = (const float*)d_in[4];
    const float* bhh     = (const float*)d_in[5];
    const float* Wfc     = (const float*)d_in[6];
    const float* bfc     = (const float*)d_in[7];

    cudaFuncSetAttribute(fused_kernel, cudaFuncAttributeMaxDynamicSharedMemorySize, SM_TOT);

    convert_wfc_kernel<<<(VOCAB * HID / 4) / 256, 256>>>(Wfc);
    fused_kernel<<<GRID, 256, SM_TOT>>>(inputs, targets, Wih, bih, Whh, bhh, bfc);
    finalize_kernel<<<1, 1024>>>((float*)d_out);
}